// round 15
// baseline (speedup 1.0000x reference)
#include <cuda_runtime.h>
#include <cuda_fp16.h>
#include <cstdint>

#define NN 100000
#define NE 1600000
#define HH 128
#define GG 64
#define BN_EPS 1e-5f
#define SCAN_B 1024
#define NSB ((NN + SCAN_B - 1) / SCAN_B)   // 98 scan blocks (all resident)

typedef unsigned int u32;

// ---------------- static device scratch (allocation-free) ----------------
// State-recycling invariant: g_indeg, g_pool, g_cnt, g_done, g_done2, g_pdone
// are zero at the START of every kernel_launch call (module-load zero-init for
// the first call; each replay re-zeroes them at last use).
__device__ __align__(16) u32   g_x16[NN * 64];   // fp16x2 activations (BN+ReLU applied)
__device__ __align__(16) u32   g_h16[NN * 64];   // fp16x2 features (dinv pre-folded)
__device__ __align__(16) __half g_w16a[HH * HH]; // W2 fp16
__device__ __align__(16) __half g_w16b[HH * HH]; // W3 fp16
__device__ float g_xs[NN * 3];
__device__ int   g_csrc[NE];
__device__ int   g_batch[NN];
__device__ int   g_indeg[NN];
__device__ int   g_rowptr[NN];
__device__ int   g_cursor[NN];
__device__ int   g_bsum[128];
__device__ int   g_boff[128];
__device__ int   g_done;
__device__ int   g_done2;
__device__ int   g_pdone;
__device__ float g_dinv[NN];
__device__ float g_pool[GG * HH];
__device__ int   g_cnt[GG];
__device__ __align__(16) float g_bns[3 * HH];
__device__ __align__(16) float g_bnt[3 * HH];

// ---------------- helpers ----------------
__device__ __forceinline__ u32 smaddr(const void* p) {
    return (u32)__cvta_generic_to_shared(p);
}
__device__ __forceinline__ void ldm_x4(u32& r0, u32& r1, u32& r2, u32& r3, u32 a) {
    asm volatile("ldmatrix.sync.aligned.m8n8.x4.shared.b16 {%0,%1,%2,%3}, [%4];"
                 : "=r"(r0), "=r"(r1), "=r"(r2), "=r"(r3) : "r"(a));
}
__device__ __forceinline__ void ldm_x4t(u32& r0, u32& r1, u32& r2, u32& r3, u32 a) {
    asm volatile("ldmatrix.sync.aligned.m8n8.x4.trans.shared.b16 {%0,%1,%2,%3}, [%4];"
                 : "=r"(r0), "=r"(r1), "=r"(r2), "=r"(r3) : "r"(a));
}
__device__ __forceinline__ void mma16816(float* c, u32 a0, u32 a1, u32 a2, u32 a3,
                                         u32 b0, u32 b1) {
    asm volatile("mma.sync.aligned.m16n8k16.row.col.f32.f16.f16.f32 "
                 "{%0,%1,%2,%3}, {%4,%5,%6,%7}, {%8,%9}, {%0,%1,%2,%3};"
                 : "+f"(c[0]), "+f"(c[1]), "+f"(c[2]), "+f"(c[3])
                 : "r"(a0), "r"(a1), "r"(a2), "r"(a3), "r"(b0), "r"(b1));
}
__device__ __forceinline__ int block_is64(const void* ei, int* sm) {
    if (threadIdx.x == 0) {
        const int* p = (const int*)ei;
        int z = 0;
        #pragma unroll
        for (int i = 0; i < 32; i++) z |= p[2 * i + 1];
        *sm = (z == 0) ? 1 : 0;
    }
    __syncthreads();
    return *sm;
}
__device__ __forceinline__ void add8(float* a, uint4 v) {
    float2 f;
    f = __half22float2(*(const __half2*)&v.x); a[0] += f.x; a[1] += f.y;
    f = __half22float2(*(const __half2*)&v.y); a[2] += f.x; a[3] += f.y;
    f = __half22float2(*(const __half2*)&v.z); a[4] += f.x; a[5] += f.y;
    f = __half22float2(*(const __half2*)&v.w); a[6] += f.x; a[7] += f.y;
}

// ---------------- init + degree count fused (edge grid) --------------------
// g_indeg arrives zeroed (module load / previous replay's agg16(2)).
__global__ void k_initcnt(const void* ei, const void* b,
                          const float* __restrict__ W2, const float* __restrict__ W3,
                          const float* b1, const float* g1, const float* be1, const float* m1, const float* v1,
                          const float* b2, const float* g2, const float* be2, const float* m2, const float* v2,
                          const float* b3, const float* g3, const float* be3, const float* m3, const float* v3) {
    __shared__ int s64;
    int is64 = block_is64(ei, &s64);
    int i = blockIdx.x * blockDim.x + threadIdx.x;

    // degree count: 2 edges per thread (dst half only)
    int e = i * 2;
    if (e < NE) {
        int d0, d1;
        if (is64) {
            longlong2 dd = *(const longlong2*)((const long long*)ei + NE + e);
            d0 = (int)dd.x; d1 = (int)dd.y;
        } else {
            int2 dd = *(const int2*)((const int*)ei + NE + e);
            d0 = dd.x; d1 = dd.y;
        }
        atomicAdd(&g_indeg[d0], 1);
        atomicAdd(&g_indeg[d1], 1);
    }
    // node / param init
    if (i < NN)
        g_batch[i] = is64 ? (int)((const long long*)b)[i] : ((const int*)b)[i];
    if (i < HH * HH) {
        g_w16a[i] = __float2half(W2[i]);
        g_w16b[i] = __float2half(W3[i]);
    }
    if (i < HH) {
        int c = i;
        float s;
        s = g1[c] * rsqrtf(v1[c] + BN_EPS);
        g_bns[c] = s;           g_bnt[c] = (b1[c] - m1[c]) * s + be1[c];
        s = g2[c] * rsqrtf(v2[c] + BN_EPS);
        g_bns[HH + c] = s;      g_bnt[HH + c] = (b2[c] - m2[c]) * s + be2[c];
        s = g3[c] * rsqrtf(v3[c] + BN_EPS);
        g_bns[2 * HH + c] = s;  g_bnt[2 * HH + c] = (b3[c] - m3[c]) * s + be3[c];
    }
}

// ---------------- fused scan: block scan + boff + finalize (resident) ------
// 98 blocks x 1024 thr, all co-resident; last-arriving block computes boff,
// releases via g_done; every block then finalizes its own nodes from regs.
__global__ __launch_bounds__(SCAN_B)
void k_scan(const float* __restrict__ x) {
    __shared__ int sm[SCAN_B];
    __shared__ int isLast;
    int tid = threadIdx.x;
    int i = blockIdx.x * SCAN_B + tid;
    int dg = (i < NN) ? g_indeg[i] : 0;
    sm[tid] = dg;
    __syncthreads();
    for (int off = 1; off < SCAN_B; off <<= 1) {
        int t = (tid >= off) ? sm[tid - off] : 0;
        __syncthreads();
        sm[tid] += t;
        __syncthreads();
    }
    int inc = sm[tid];   // inclusive scan value (register)
    if (tid == SCAN_B - 1) g_bsum[blockIdx.x] = sm[SCAN_B - 1];
    __threadfence();
    if (tid == 0)
        isLast = (atomicAdd(&g_done, 1) == NSB - 1);
    __syncthreads();
    if (isLast) {
        int bv = 0;
        if (tid < 128) {
            bv = (tid < NSB) ? g_bsum[tid] : 0;
            sm[tid] = bv;
        }
        __syncthreads();
        for (int off = 1; off < 128; off <<= 1) {
            int u = (tid >= off && tid < 128) ? sm[tid - off] : 0;
            __syncthreads();
            if (tid < 128) sm[tid] += u;
            __syncthreads();
        }
        if (tid < 128) g_boff[tid] = sm[tid] - bv;   // exclusive
        __threadfence();
        if (tid == 0) atomicAdd(&g_done, 1);         // release: g_done = NSB+1
    } else {
        if (tid == 0)
            while (*(volatile int*)&g_done <= NSB) { }
        __syncthreads();
    }

    // finalize from registers (no g_scan array, no reloads)
    if (i < NN) {
        int ex = inc - dg + g_boff[blockIdx.x];
        g_rowptr[i] = ex;
        g_cursor[i] = ex;
        float di = rsqrtf((float)(dg + 1));
        g_dinv[i] = di;
        g_xs[i * 3 + 0] = x[i * 3 + 0] * di;
        g_xs[i * 3 + 1] = x[i * 3 + 1] * di;
        g_xs[i * 3 + 2] = x[i * 3 + 2] * di;
    }
    __syncthreads();
    if (tid == 0) {
        if (atomicAdd(&g_done2, 1) == NSB - 1) {   // last to finish resets
            g_done = 0;
            g_done2 = 0;
            __threadfence();
        }
    }
}

// ---------------- CSR fill: reads ei directly ----------------
__global__ void k_fill(const void* ei) {
    __shared__ int s64;
    int is64 = block_is64(ei, &s64);
    int e = blockIdx.x * blockDim.x + threadIdx.x;
    if (e >= NE) return;
    int s, d;
    if (is64) {
        const long long* p = (const long long*)ei;
        s = (int)p[e];  d = (int)p[NE + e];
    } else {
        const int* p = (const int*)ei;
        s = p[e];       d = p[NE + e];
    }
    int pos = atomicAdd(&g_cursor[d], 1);
    g_csrc[pos] = s;
}

// ---------------- fused layer-1: 3-dim agg + W1 + BN1+ReLU -> fp16 g_x16 ---
__global__ __launch_bounds__(256)
void k_l1(const float* __restrict__ W1) {
    __shared__ float sxa[128][3];
    __shared__ float sW[3][HH];
    __shared__ float sS[HH], sT[HH];
    int tid = threadIdx.x;
    int m0 = blockIdx.x * 128;

    if (tid < HH) {
        sW[0][tid] = W1[tid];
        sW[1][tid] = W1[HH + tid];
        sW[2][tid] = W1[2 * HH + tid];
        sS[tid] = g_bns[tid];
        sT[tid] = g_bnt[tid];
    }

    {   // phase 1: aggregate 3-dim xs; 2 threads per node
        int r = tid >> 1, half = tid & 1;
        int n = m0 + r;
        float a0 = 0.f, a1 = 0.f, a2 = 0.f;
        if (n < NN) {
            int start = g_rowptr[n];
            int cnt = g_indeg[n];
            for (int j = half; j < cnt; j += 2) {
                int s = g_csrc[start + j];
                a0 += g_xs[s * 3 + 0];
                a1 += g_xs[s * 3 + 1];
                a2 += g_xs[s * 3 + 2];
            }
            if (half == 0) {
                a0 += g_xs[n * 3 + 0];
                a1 += g_xs[n * 3 + 1];
                a2 += g_xs[n * 3 + 2];
            }
        }
        if (half == 1) {
            sxa[r][0] = a0; sxa[r][1] = a1; sxa[r][2] = a2;
        }
        __syncthreads();
        if (half == 0 && n < NN) {
            float di = g_dinv[n];
            sxa[r][0] = (a0 + sxa[r][0]) * di;
            sxa[r][1] = (a1 + sxa[r][1]) * di;
            sxa[r][2] = (a2 + sxa[r][2]) * di;
        }
        __syncthreads();
    }

    {   // phase 2: warp per 16 nodes; lane -> 4 channels; coalesced stores
        int w = tid >> 5, lane = tid & 31;
        int c0 = lane * 4;
        float w00 = sW[0][c0],     w10 = sW[1][c0],     w20 = sW[2][c0];
        float w01 = sW[0][c0 + 1], w11 = sW[1][c0 + 1], w21 = sW[2][c0 + 1];
        float w02 = sW[0][c0 + 2], w12 = sW[1][c0 + 2], w22 = sW[2][c0 + 2];
        float w03 = sW[0][c0 + 3], w13 = sW[1][c0 + 3], w23 = sW[2][c0 + 3];
        float s0 = sS[c0], s1 = sS[c0 + 1], s2 = sS[c0 + 2], s3 = sS[c0 + 3];
        float t0 = sT[c0], t1 = sT[c0 + 1], t2 = sT[c0 + 2], t3 = sT[c0 + 3];
        #pragma unroll 4
        for (int k = 0; k < 16; k++) {
            int r = w * 16 + k;
            int n = m0 + r;
            if (n >= NN) break;
            float x0 = sxa[r][0], x1 = sxa[r][1], x2 = sxa[r][2];
            float v0 = x0 * w00 + x1 * w10 + x2 * w20;
            float v1 = x0 * w01 + x1 * w11 + x2 * w21;
            float v2 = x0 * w02 + x1 * w12 + x2 * w22;
            float v3 = x0 * w03 + x1 * w13 + x2 * w23;
            v0 = fmaxf(fmaf(v0, s0, t0), 0.f);
            v1 = fmaxf(fmaf(v1, s1, t1), 0.f);
            v2 = fmaxf(fmaf(v2, s2, t2), 0.f);
            v3 = fmaxf(fmaf(v3, s3, t3), 0.f);
            __half2 h0 = __floats2half2_rn(v0, v1);
            __half2 h1 = __floats2half2_rn(v2, v3);
            uint2 o2 = make_uint2(*(u32*)&h0, *(u32*)&h1);
            *(uint2*)&g_x16[n * 64 + lane * 2] = o2;
        }
    }
}

// ---------------- HMMA fp16 GEMM, 32 rows x 64 cols per warp ---------------
__global__ __launch_bounds__(256, 2)
void k_gemmh(int wSel) {
    __shared__ __align__(16) __half Xs[128][72];
    __shared__ __align__(16) __half Wsm[64][136];
    const __half* __restrict__ Wh = wSel ? g_w16b : g_w16a;
    int tid = threadIdx.x;
    int warp = tid >> 5, lane = tid & 31;
    int rg = warp >> 1;
    int cg = warp & 1;
    int m0 = blockIdx.x * 128;
    float c[2][8][4] = {};

    for (int kt = 0; kt < 128; kt += 64) {
        {
            int r = tid >> 1;
            int n = m0 + r;
            int base = n * 64 + (kt >> 1) + (tid & 1) * 16;
            int cs = (tid & 1) * 32;
            if (n < NN) {
                #pragma unroll
                for (int j = 0; j < 4; j++) {
                    uint4 v = *(const uint4*)&g_x16[base + j * 4];
                    *(uint4*)&Xs[r][cs + j * 8] = v;
                }
            } else {
                #pragma unroll
                for (int j = 0; j < 4; j++)
                    *(uint4*)&Xs[r][cs + j * 8] = make_uint4(0, 0, 0, 0);
            }
        }
        {
            int kk = tid >> 2, ns = (tid & 3) * 32;
            #pragma unroll
            for (int j = 0; j < 4; j++) {
                uint4 w = *(const uint4*)&Wh[(kt + kk) * HH + ns + j * 8];
                *(uint4*)&Wsm[kk][ns + j * 8] = w;
            }
        }
        __syncthreads();

        #pragma unroll
        for (int ks = 0; ks < 4; ks++) {
            u32 a[2][4];
            #pragma unroll
            for (int mt = 0; mt < 2; mt++) {
                u32 aaddr = smaddr(&Xs[rg * 32 + mt * 16 + (lane & 7) + 8 * ((lane >> 3) & 1)]
                                      [ks * 16 + 8 * (lane >> 4)]);
                ldm_x4(a[mt][0], a[mt][1], a[mt][2], a[mt][3], aaddr);
            }
            u32 b[4][4];
            #pragma unroll
            for (int nt = 0; nt < 4; nt++) {
                u32 baddr = smaddr(&Wsm[ks * 16 + (lane & 7) + 8 * ((lane >> 3) & 1)]
                                      [cg * 64 + nt * 16 + 8 * (lane >> 4)]);
                ldm_x4t(b[nt][0], b[nt][1], b[nt][2], b[nt][3], baddr);
            }
            #pragma unroll
            for (int mt = 0; mt < 2; mt++) {
                #pragma unroll
                for (int nt = 0; nt < 4; nt++) {
                    mma16816(c[mt][2 * nt],     a[mt][0], a[mt][1], a[mt][2], a[mt][3],
                             b[nt][0], b[nt][1]);
                    mma16816(c[mt][2 * nt + 1], a[mt][0], a[mt][1], a[mt][2], a[mt][3],
                             b[nt][2], b[nt][3]);
                }
            }
        }
        __syncthreads();
    }

    #pragma unroll
    for (int mt = 0; mt < 2; mt++) {
        int r0 = m0 + rg * 32 + mt * 16 + (lane >> 2);
        int r1 = r0 + 8;
        float d0 = (r0 < NN) ? g_dinv[r0] : 0.f;
        float d1 = (r1 < NN) ? g_dinv[r1] : 0.f;
        #pragma unroll
        for (int nt = 0; nt < 8; nt++) {
            int col2 = cg * 32 + nt * 4 + (lane & 3);
            if (r0 < NN) {
                __half2 h = __floats2half2_rn(c[mt][nt][0] * d0, c[mt][nt][1] * d0);
                g_h16[r0 * 64 + col2] = *(u32*)&h;
            }
            if (r1 < NN) {
                __half2 h = __floats2half2_rn(c[mt][nt][2] * d1, c[mt][nt][3] * d1);
                g_h16[r1 * 64 + col2] = *(u32*)&h;
            }
        }
    }
}

// ---------------- gather agg: warp per node, paired-edge uint4 -------------
// clearDeg: last consumer of g_indeg zeroes it for the next replay.
__global__ __launch_bounds__(256)
void k_agg16(int layer, int clearDeg) {
    int n = (blockIdx.x * 256 + threadIdx.x) >> 5;
    int lane = threadIdx.x & 31;
    if (n >= NN) return;
    int half = lane >> 4, sub = lane & 15;
    float din = g_dinv[n];
    int start = g_rowptr[n];
    int cnt = g_indeg[n];
    if (clearDeg && lane == 0) g_indeg[n] = 0;
    const uint4* __restrict__ H4 = (const uint4*)g_h16;

    float acc[8] = {0.f, 0.f, 0.f, 0.f, 0.f, 0.f, 0.f, 0.f};
    if (half == 0) add8(acc, H4[n * 16 + sub]);   // self term

    int j = 0;
    for (; j + 3 < cnt; j += 4) {
        int sA = g_csrc[start + j + half];
        int sB = g_csrc[start + j + 2 + half];
        uint4 vA = H4[sA * 16 + sub];
        uint4 vB = H4[sB * 16 + sub];
        add8(acc, vA);
        add8(acc, vB);
    }
    if (j + 1 < cnt) {
        int sA = g_csrc[start + j + half];
        add8(acc, H4[sA * 16 + sub]);
        j += 2;
    }
    if (j < cnt && half == 0) {
        int s = g_csrc[start + j];
        add8(acc, H4[s * 16 + sub]);
    }
    #pragma unroll
    for (int k = 0; k < 8; k++)
        acc[k] += __shfl_xor_sync(0xffffffffu, acc[k], 16);

    if (half == 0) {
        const float4* S4 = (const float4*)&g_bns[layer * HH + sub * 8];
        const float4* T4 = (const float4*)&g_bnt[layer * HH + sub * 8];
        float4 s0 = S4[0], s1 = S4[1];
        float4 t0 = T4[0], t1 = T4[1];
        float e0 = fmaxf(fmaf(acc[0] * din, s0.x, t0.x), 0.f);
        float e1 = fmaxf(fmaf(acc[1] * din, s0.y, t0.y), 0.f);
        float e2 = fmaxf(fmaf(acc[2] * din, s0.z, t0.z), 0.f);
        float e3 = fmaxf(fmaf(acc[3] * din, s0.w, t0.w), 0.f);
        float e4 = fmaxf(fmaf(acc[4] * din, s1.x, t1.x), 0.f);
        float e5 = fmaxf(fmaf(acc[5] * din, s1.y, t1.y), 0.f);
        float e6 = fmaxf(fmaf(acc[6] * din, s1.z, t1.z), 0.f);
        float e7 = fmaxf(fmaf(acc[7] * din, s1.w, t1.w), 0.f);
        __half2 h0 = __floats2half2_rn(e0, e1);
        __half2 h1 = __floats2half2_rn(e2, e3);
        __half2 h2 = __floats2half2_rn(e4, e5);
        __half2 h3 = __floats2half2_rn(e6, e7);
        uint4 o = make_uint4(*(u32*)&h0, *(u32*)&h1, *(u32*)&h2, *(u32*)&h3);
        ((uint4*)g_x16)[n * 16 + sub] = o;
    }
}

// ---------------- mean pool + fused head; last block also recycles state ---
#define NPB 128
#define POOL_BLOCKS ((NN + NPB - 1) / NPB)
__global__ __launch_bounds__(64)
void k_poolhead(const float* __restrict__ lin_W, const float* __restrict__ lin_b,
                float* __restrict__ out) {
    __shared__ int sLast;
    int c2 = threadIdx.x;   // half2 column 0..63
    int n0 = blockIdx.x * NPB;
    int n1 = n0 + NPB; if (n1 > NN) n1 = NN;

    if (n0 < NN) {
        float ax = 0.f, ay = 0.f;
        int cur = g_batch[n0];
        int cnt = 0;
        for (int n = n0; n < n1; n++) {
            int g = g_batch[n];
            if (g != cur) {
                atomicAdd(&g_pool[cur * HH + 2 * c2], ax);
                atomicAdd(&g_pool[cur * HH + 2 * c2 + 1], ay);
                if (c2 == 0) atomicAdd(&g_cnt[cur], cnt);
                ax = 0.f; ay = 0.f; cnt = 0; cur = g;
            }
            u32 v = g_x16[n * 64 + c2];
            float2 f = __half22float2(*(const __half2*)&v);
            ax += f.x; ay += f.y;
            cnt++;
        }
        atomicAdd(&g_pool[cur * HH + 2 * c2], ax);
        atomicAdd(&g_pool[cur * HH + 2 * c2 + 1], ay);
        if (c2 == 0) atomicAdd(&g_cnt[cur], cnt);
    }

    __syncthreads();
    if (threadIdx.x == 0) {
        __threadfence();
        sLast = (atomicAdd(&g_pdone, 1) == POOL_BLOCKS - 1) ? 1 : 0;
    }
    __syncthreads();
    if (sLast) {
        __threadfence();
        int g = threadIdx.x;   // 0..63 graphs
        float inv = 1.f / fmaxf((float)g_cnt[g], 1.f);
        float a0 = 0.f, a1 = 0.f;
        #pragma unroll 8
        for (int c = 0; c < HH; c++) {
            float p = g_pool[g * HH + c] * inv;
            a0 += p * lin_W[c * 2 + 0];
            a1 += p * lin_W[c * 2 + 1];
        }
        out[g * 2 + 0] = a0 + lin_b[0];
        out[g * 2 + 1] = a1 + lin_b[1];
        // recycle state for next replay
        for (int idx = threadIdx.x; idx < GG * HH; idx += 64)
            g_pool[idx] = 0.f;
        if (threadIdx.x < GG) g_cnt[threadIdx.x] = 0;
        if (threadIdx.x == 0) g_pdone = 0;
    }
}

// ---------------- launch ----------------
extern "C" void kernel_launch(void* const* d_in, const int* in_sizes, int n_in,
                              void* d_out, int out_size) {
    const float* x     = (const float*)d_in[0];
    const void*  ei    = d_in[1];
    const void*  batch = d_in[2];
    const float* W1 = (const float*)d_in[3];
    const float* b1 = (const float*)d_in[4];
    const float* W2 = (const float*)d_in[5];
    const float* b2 = (const float*)d_in[6];
    const float* W3 = (const float*)d_in[7];
    const float* b3 = (const float*)d_in[8];
    const float* lin_W = (const float*)d_in[9];
    const float* lin_b = (const float*)d_in[10];
    const float* bn1g = (const float*)d_in[11];
    const float* bn1b = (const float*)d_in[12];
    const float* bn1m = (const float*)d_in[13];
    const float* bn1v = (const float*)d_in[14];
    const float* bn2g = (const float*)d_in[15];
    const float* bn2b = (const float*)d_in[16];
    const float* bn2m = (const float*)d_in[17];
    const float* bn2v = (const float*)d_in[18];
    const float* bn3g = (const float*)d_in[19];
    const float* bn3b = (const float*)d_in[20];
    const float* bn3m = (const float*)d_in[21];
    const float* bn3v = (const float*)d_in[22];
    float* out = (float*)d_out;

    const int TB = 256;
    const int ebl  = (NE + TB - 1) / TB;        // 1 edge/thread (fill)
    const int e2bl = (NE / 2 + TB - 1) / TB;    // 2 edges/thread (init+count)
    const int abl = (NN * 32 + TB - 1) / TB;

    k_initcnt<<<e2bl, TB>>>(ei, batch, W2, W3,                 // 0
                            b1, bn1g, bn1b, bn1m, bn1v,
                            b2, bn2g, bn2b, bn2m, bn2v,
                            b3, bn3g, bn3b, bn3m, bn3v);
    k_scan<<<NSB, SCAN_B>>>(x);                                // 1  (scan + finalize)
    k_fill<<<ebl, TB>>>(ei);                                   // 2

    k_l1<<<(NN + 127) / 128, 256>>>(W1);                       // 3  <- profiled

    k_gemmh<<<(NN + 127) / 128, 256>>>(0);                     // 4  -> g_h16
    k_agg16<<<abl, TB>>>(1, 0);                                // 5  -> g_x16 (BN2)

    k_gemmh<<<(NN + 127) / 128, 256>>>(1);                     // 6  -> g_h16
    k_agg16<<<abl, TB>>>(2, 1);                                // 7  -> g_x16 (BN3), clears indeg

    k_poolhead<<<POOL_BLOCKS, 64>>>(lin_W, lin_b, out);        // 8
}

// round 16
// speedup vs baseline: 1.2966x; 1.2966x over previous
#include <cuda_runtime.h>
#include <cuda_fp16.h>
#include <cstdint>

#define NN 100000
#define NE 1600000
#define HH 128
#define GG 64
#define BN_EPS 1e-5f
#define SCAN_B 1024
#define NSB ((NN + SCAN_B - 1) / SCAN_B)   // 98 scan blocks

typedef unsigned int u32;

// ---------------- static device scratch (allocation-free) ----------------
__device__ __align__(16) u32   g_x16[NN * 64];   // fp16x2 activations (BN+ReLU applied)
__device__ __align__(16) u32   g_h16[NN * 64];   // fp16x2 features (dinv pre-folded)
__device__ __align__(16) __half g_w16a[HH * HH]; // W2 fp16
__device__ __align__(16) __half g_w16b[HH * HH]; // W3 fp16
__device__ float g_xs[NN * 3];
__device__ int   g_csrc[NE];
__device__ int   g_batch[NN];
__device__ int   g_indeg[NN];
__device__ int   g_scan[NN];
__device__ int   g_rowptr[NN];
__device__ int   g_cursor[NN];
__device__ int   g_bsum[128];
__device__ int   g_boff[128];
__device__ int   g_done;
__device__ int   g_pdone;
__device__ float g_dinv[NN];
__device__ float g_pool[GG * HH];
__device__ int   g_cnt[GG];
__device__ __align__(16) float g_bns[3 * HH];
__device__ __align__(16) float g_bnt[3 * HH];

// ---------------- helpers ----------------
__device__ __forceinline__ u32 smaddr(const void* p) {
    return (u32)__cvta_generic_to_shared(p);
}
__device__ __forceinline__ void ldm_x4(u32& r0, u32& r1, u32& r2, u32& r3, u32 a) {
    asm volatile("ldmatrix.sync.aligned.m8n8.x4.shared.b16 {%0,%1,%2,%3}, [%4];"
                 : "=r"(r0), "=r"(r1), "=r"(r2), "=r"(r3) : "r"(a));
}
__device__ __forceinline__ void ldm_x4t(u32& r0, u32& r1, u32& r2, u32& r3, u32 a) {
    asm volatile("ldmatrix.sync.aligned.m8n8.x4.trans.shared.b16 {%0,%1,%2,%3}, [%4];"
                 : "=r"(r0), "=r"(r1), "=r"(r2), "=r"(r3) : "r"(a));
}
__device__ __forceinline__ void mma16816(float* c, u32 a0, u32 a1, u32 a2, u32 a3,
                                         u32 b0, u32 b1) {
    asm volatile("mma.sync.aligned.m16n8k16.row.col.f32.f16.f16.f32 "
                 "{%0,%1,%2,%3}, {%4,%5,%6,%7}, {%8,%9}, {%0,%1,%2,%3};"
                 : "+f"(c[0]), "+f"(c[1]), "+f"(c[2]), "+f"(c[3])
                 : "r"(a0), "r"(a1), "r"(a2), "r"(a3), "r"(b0), "r"(b1));
}
__device__ __forceinline__ int block_is64(const void* ei, int* sm) {
    if (threadIdx.x == 0) {
        const int* p = (const int*)ei;
        int z = 0;
        #pragma unroll
        for (int i = 0; i < 32; i++) z |= p[2 * i + 1];
        *sm = (z == 0) ? 1 : 0;
    }
    __syncthreads();
    return *sm;
}
__device__ __forceinline__ void add8(float* a, uint4 v) {
    float2 f;
    f = __half22float2(*(const __half2*)&v.x); a[0] += f.x; a[1] += f.y;
    f = __half22float2(*(const __half2*)&v.y); a[2] += f.x; a[3] += f.y;
    f = __half22float2(*(const __half2*)&v.z); a[4] += f.x; a[5] += f.y;
    f = __half22float2(*(const __half2*)&v.w); a[6] += f.x; a[7] += f.y;
}

// ---------------- init: zero state + batch cvt + W fp16 + BN affine --------
__global__ void k_init(const void* ei, const void* b,
                       const float* __restrict__ W2, const float* __restrict__ W3,
                       const float* b1, const float* g1, const float* be1, const float* m1, const float* v1,
                       const float* b2, const float* g2, const float* be2, const float* m2, const float* v2,
                       const float* b3, const float* g3, const float* be3, const float* m3, const float* v3) {
    __shared__ int s64;
    int is64 = block_is64(ei, &s64);
    int i = blockIdx.x * blockDim.x + threadIdx.x;
    if (i < NN) {
        g_indeg[i] = 0;
        g_batch[i] = is64 ? (int)((const long long*)b)[i] : ((const int*)b)[i];
    }
    if (i < GG * HH) g_pool[i] = 0.f;
    if (i < GG) g_cnt[i] = 0;
    if (i == 0) { g_done = 0; g_pdone = 0; }
    if (i < HH * HH) {
        g_w16a[i] = __float2half(W2[i]);
        g_w16b[i] = __float2half(W3[i]);
    }
    if (i < HH) {
        int c = i;
        float s;
        s = g1[c] * rsqrtf(v1[c] + BN_EPS);
        g_bns[c] = s;           g_bnt[c] = (b1[c] - m1[c]) * s + be1[c];
        s = g2[c] * rsqrtf(v2[c] + BN_EPS);
        g_bns[HH + c] = s;      g_bnt[HH + c] = (b2[c] - m2[c]) * s + be2[c];
        s = g3[c] * rsqrtf(v3[c] + BN_EPS);
        g_bns[2 * HH + c] = s;  g_bnt[2 * HH + c] = (b3[c] - m3[c]) * s + be3[c];
    }
}

// ---------------- count in-degree directly from ei (dst half only) ---------
__global__ void k_cvt_count(const void* ei) {
    __shared__ int s64;
    int is64 = block_is64(ei, &s64);
    int t = blockIdx.x * blockDim.x + threadIdx.x;
    int e = t * 2;
    if (e >= NE) return;
    int d0, d1;
    if (is64) {
        longlong2 dd = *(const longlong2*)((const long long*)ei + NE + e);
        d0 = (int)dd.x; d1 = (int)dd.y;
    } else {
        int2 dd = *(const int2*)((const int*)ei + NE + e);
        d0 = dd.x; d1 = dd.y;
    }
    atomicAdd(&g_indeg[d0], 1);
    atomicAdd(&g_indeg[d1], 1);
}

// ---------------- scan1: per-block inclusive scan; last block scans bsums --
__global__ __launch_bounds__(SCAN_B)
void k_scan1() {
    __shared__ int sm[SCAN_B];
    __shared__ int isLast;
    int i = blockIdx.x * SCAN_B + threadIdx.x;
    int v = (i < NN) ? g_indeg[i] : 0;
    sm[threadIdx.x] = v;
    __syncthreads();
    for (int off = 1; off < SCAN_B; off <<= 1) {
        int t = (threadIdx.x >= off) ? sm[threadIdx.x - off] : 0;
        __syncthreads();
        sm[threadIdx.x] += t;
        __syncthreads();
    }
    if (i < NN) g_scan[i] = sm[threadIdx.x];
    if (threadIdx.x == SCAN_B - 1) g_bsum[blockIdx.x] = sm[SCAN_B - 1];
    __threadfence();
    if (threadIdx.x == 0)
        isLast = (atomicAdd(&g_done, 1) == (int)gridDim.x - 1);
    __syncthreads();
    if (isLast) {
        __threadfence();
        int t = threadIdx.x;
        int bv = 0;
        if (t < 128) {
            bv = (t < NSB) ? g_bsum[t] : 0;
            sm[t] = bv;
        }
        __syncthreads();
        for (int off = 1; off < 128; off <<= 1) {
            int u = (t >= off && t < 128) ? sm[t - off] : 0;
            __syncthreads();
            if (t < 128) sm[t] += u;
            __syncthreads();
        }
        if (t < 128) g_boff[t] = sm[t] - bv;   // exclusive
    }
}

// ---------------- scan finalize + dinv + xs = x*dinv ----------------
__global__ void k_scan3(const float* __restrict__ x) {
    int i = blockIdx.x * blockDim.x + threadIdx.x;
    if (i >= NN) return;
    int dg = g_indeg[i];
    int ex = g_scan[i] - dg + g_boff[i >> 10];
    g_rowptr[i] = ex;
    g_cursor[i] = ex;
    float di = rsqrtf((float)(dg + 1));
    g_dinv[i] = di;
    g_xs[i * 3 + 0] = x[i * 3 + 0] * di;
    g_xs[i * 3 + 1] = x[i * 3 + 1] * di;
    g_xs[i * 3 + 2] = x[i * 3 + 2] * di;
}

// ---------------- CSR fill: reads ei directly ----------------
__global__ void k_fill(const void* ei) {
    __shared__ int s64;
    int is64 = block_is64(ei, &s64);
    int e = blockIdx.x * blockDim.x + threadIdx.x;
    if (e >= NE) return;
    int s, d;
    if (is64) {
        const long long* p = (const long long*)ei;
        s = (int)p[e];  d = (int)p[NE + e];
    } else {
        const int* p = (const int*)ei;
        s = p[e];       d = p[NE + e];
    }
    int pos = atomicAdd(&g_cursor[d], 1);
    g_csrc[pos] = s;
}

// ---------------- fused layer-1 v2: 4 threads/node gather ------------------
// block = 64 nodes, 256 threads.
// phase 1: 4 threads per node stride edges; quad shfl-reduce.
// phase 2: warp per 8 nodes; lane -> 4 channels; coalesced uint2 stores.
__global__ __launch_bounds__(256)
void k_l1(const float* __restrict__ W1) {
    __shared__ float sxa[64][3];
    __shared__ float sW[3][HH];
    __shared__ float sS[HH], sT[HH];
    int tid = threadIdx.x;
    int m0 = blockIdx.x * 64;

    if (tid < HH) {
        sW[0][tid] = W1[tid];
        sW[1][tid] = W1[HH + tid];
        sW[2][tid] = W1[2 * HH + tid];
        sS[tid] = g_bns[tid];
        sT[tid] = g_bnt[tid];
    }

    {   // phase 1: 4 threads per node
        int r = tid >> 2, q = tid & 3;
        int n = m0 + r;
        float a0 = 0.f, a1 = 0.f, a2 = 0.f;
        if (n < NN) {
            int start = g_rowptr[n];
            int cnt = g_indeg[n];
            for (int j = q; j < cnt; j += 4) {
                int s = g_csrc[start + j];
                a0 += g_xs[s * 3 + 0];
                a1 += g_xs[s * 3 + 1];
                a2 += g_xs[s * 3 + 2];
            }
            if (q == 0) {
                a0 += g_xs[n * 3 + 0];
                a1 += g_xs[n * 3 + 1];
                a2 += g_xs[n * 3 + 2];
            }
        }
        // quad reduce (lanes 4k..4k+3 are one node)
        a0 += __shfl_xor_sync(0xffffffffu, a0, 1);
        a1 += __shfl_xor_sync(0xffffffffu, a1, 1);
        a2 += __shfl_xor_sync(0xffffffffu, a2, 1);
        a0 += __shfl_xor_sync(0xffffffffu, a0, 2);
        a1 += __shfl_xor_sync(0xffffffffu, a1, 2);
        a2 += __shfl_xor_sync(0xffffffffu, a2, 2);
        if (q == 0 && n < NN) {
            float di = g_dinv[n];
            sxa[r][0] = a0 * di;
            sxa[r][1] = a1 * di;
            sxa[r][2] = a2 * di;
        }
        __syncthreads();
    }

    {   // phase 2: warp per 8 nodes
        int w = tid >> 5, lane = tid & 31;
        int c0 = lane * 4;
        float w00 = sW[0][c0],     w10 = sW[1][c0],     w20 = sW[2][c0];
        float w01 = sW[0][c0 + 1], w11 = sW[1][c0 + 1], w21 = sW[2][c0 + 1];
        float w02 = sW[0][c0 + 2], w12 = sW[1][c0 + 2], w22 = sW[2][c0 + 2];
        float w03 = sW[0][c0 + 3], w13 = sW[1][c0 + 3], w23 = sW[2][c0 + 3];
        float s0 = sS[c0], s1 = sS[c0 + 1], s2 = sS[c0 + 2], s3 = sS[c0 + 3];
        float t0 = sT[c0], t1 = sT[c0 + 1], t2 = sT[c0 + 2], t3 = sT[c0 + 3];
        #pragma unroll
        for (int k = 0; k < 8; k++) {
            int r = w * 8 + k;
            int n = m0 + r;
            if (n >= NN) break;
            float x0 = sxa[r][0], x1 = sxa[r][1], x2 = sxa[r][2];
            float v0 = x0 * w00 + x1 * w10 + x2 * w20;
            float v1 = x0 * w01 + x1 * w11 + x2 * w21;
            float v2 = x0 * w02 + x1 * w12 + x2 * w22;
            float v3 = x0 * w03 + x1 * w13 + x2 * w23;
            v0 = fmaxf(fmaf(v0, s0, t0), 0.f);
            v1 = fmaxf(fmaf(v1, s1, t1), 0.f);
            v2 = fmaxf(fmaf(v2, s2, t2), 0.f);
            v3 = fmaxf(fmaf(v3, s3, t3), 0.f);
            __half2 h0 = __floats2half2_rn(v0, v1);
            __half2 h1 = __floats2half2_rn(v2, v3);
            uint2 o2 = make_uint2(*(u32*)&h0, *(u32*)&h1);
            *(uint2*)&g_x16[n * 64 + lane * 2] = o2;
        }
    }
}

// ---------------- HMMA fp16 GEMM, 32 rows x 64 cols per warp ---------------
__global__ __launch_bounds__(256, 2)
void k_gemmh(int wSel) {
    __shared__ __align__(16) __half Xs[128][72];
    __shared__ __align__(16) __half Wsm[64][136];
    const __half* __restrict__ Wh = wSel ? g_w16b : g_w16a;
    int tid = threadIdx.x;
    int warp = tid >> 5, lane = tid & 31;
    int rg = warp >> 1;
    int cg = warp & 1;
    int m0 = blockIdx.x * 128;
    float c[2][8][4] = {};

    for (int kt = 0; kt < 128; kt += 64) {
        {
            int r = tid >> 1;
            int n = m0 + r;
            int base = n * 64 + (kt >> 1) + (tid & 1) * 16;
            int cs = (tid & 1) * 32;
            if (n < NN) {
                #pragma unroll
                for (int j = 0; j < 4; j++) {
                    uint4 v = *(const uint4*)&g_x16[base + j * 4];
                    *(uint4*)&Xs[r][cs + j * 8] = v;
                }
            } else {
                #pragma unroll
                for (int j = 0; j < 4; j++)
                    *(uint4*)&Xs[r][cs + j * 8] = make_uint4(0, 0, 0, 0);
            }
        }
        {
            int kk = tid >> 2, ns = (tid & 3) * 32;
            #pragma unroll
            for (int j = 0; j < 4; j++) {
                uint4 w = *(const uint4*)&Wh[(kt + kk) * HH + ns + j * 8];
                *(uint4*)&Wsm[kk][ns + j * 8] = w;
            }
        }
        __syncthreads();

        #pragma unroll
        for (int ks = 0; ks < 4; ks++) {
            u32 a[2][4];
            #pragma unroll
            for (int mt = 0; mt < 2; mt++) {
                u32 aaddr = smaddr(&Xs[rg * 32 + mt * 16 + (lane & 7) + 8 * ((lane >> 3) & 1)]
                                      [ks * 16 + 8 * (lane >> 4)]);
                ldm_x4(a[mt][0], a[mt][1], a[mt][2], a[mt][3], aaddr);
            }
            u32 b[4][4];
            #pragma unroll
            for (int nt = 0; nt < 4; nt++) {
                u32 baddr = smaddr(&Wsm[ks * 16 + (lane & 7) + 8 * ((lane >> 3) & 1)]
                                      [cg * 64 + nt * 16 + 8 * (lane >> 4)]);
                ldm_x4t(b[nt][0], b[nt][1], b[nt][2], b[nt][3], baddr);
            }
            #pragma unroll
            for (int mt = 0; mt < 2; mt++) {
                #pragma unroll
                for (int nt = 0; nt < 4; nt++) {
                    mma16816(c[mt][2 * nt],     a[mt][0], a[mt][1], a[mt][2], a[mt][3],
                             b[nt][0], b[nt][1]);
                    mma16816(c[mt][2 * nt + 1], a[mt][0], a[mt][1], a[mt][2], a[mt][3],
                             b[nt][2], b[nt][3]);
                }
            }
        }
        __syncthreads();
    }

    #pragma unroll
    for (int mt = 0; mt < 2; mt++) {
        int r0 = m0 + rg * 32 + mt * 16 + (lane >> 2);
        int r1 = r0 + 8;
        float d0 = (r0 < NN) ? g_dinv[r0] : 0.f;
        float d1 = (r1 < NN) ? g_dinv[r1] : 0.f;
        #pragma unroll
        for (int nt = 0; nt < 8; nt++) {
            int col2 = cg * 32 + nt * 4 + (lane & 3);
            if (r0 < NN) {
                __half2 h = __floats2half2_rn(c[mt][nt][0] * d0, c[mt][nt][1] * d0);
                g_h16[r0 * 64 + col2] = *(u32*)&h;
            }
            if (r1 < NN) {
                __half2 h = __floats2half2_rn(c[mt][nt][2] * d1, c[mt][nt][3] * d1);
                g_h16[r1 * 64 + col2] = *(u32*)&h;
            }
        }
    }
}

// ---------------- gather agg: warp per node, paired-edge uint4 -------------
__global__ __launch_bounds__(256)
void k_agg16(int layer) {
    int n = (blockIdx.x * 256 + threadIdx.x) >> 5;
    int lane = threadIdx.x & 31;
    if (n >= NN) return;
    int half = lane >> 4, sub = lane & 15;
    float din = g_dinv[n];
    int start = g_rowptr[n];
    int cnt = g_indeg[n];
    const uint4* __restrict__ H4 = (const uint4*)g_h16;

    float acc[8] = {0.f, 0.f, 0.f, 0.f, 0.f, 0.f, 0.f, 0.f};
    if (half == 0) add8(acc, H4[n * 16 + sub]);   // self term

    int j = 0;
    for (; j + 3 < cnt; j += 4) {
        int sA = g_csrc[start + j + half];
        int sB = g_csrc[start + j + 2 + half];
        uint4 vA = H4[sA * 16 + sub];
        uint4 vB = H4[sB * 16 + sub];
        add8(acc, vA);
        add8(acc, vB);
    }
    if (j + 1 < cnt) {
        int sA = g_csrc[start + j + half];
        add8(acc, H4[sA * 16 + sub]);
        j += 2;
    }
    if (j < cnt && half == 0) {
        int s = g_csrc[start + j];
        add8(acc, H4[s * 16 + sub]);
    }
    #pragma unroll
    for (int k = 0; k < 8; k++)
        acc[k] += __shfl_xor_sync(0xffffffffu, acc[k], 16);

    if (half == 0) {
        const float4* S4 = (const float4*)&g_bns[layer * HH + sub * 8];
        const float4* T4 = (const float4*)&g_bnt[layer * HH + sub * 8];
        float4 s0 = S4[0], s1 = S4[1];
        float4 t0 = T4[0], t1 = T4[1];
        float e0 = fmaxf(fmaf(acc[0] * din, s0.x, t0.x), 0.f);
        float e1 = fmaxf(fmaf(acc[1] * din, s0.y, t0.y), 0.f);
        float e2 = fmaxf(fmaf(acc[2] * din, s0.z, t0.z), 0.f);
        float e3 = fmaxf(fmaf(acc[3] * din, s0.w, t0.w), 0.f);
        float e4 = fmaxf(fmaf(acc[4] * din, s1.x, t1.x), 0.f);
        float e5 = fmaxf(fmaf(acc[5] * din, s1.y, t1.y), 0.f);
        float e6 = fmaxf(fmaf(acc[6] * din, s1.z, t1.z), 0.f);
        float e7 = fmaxf(fmaf(acc[7] * din, s1.w, t1.w), 0.f);
        __half2 h0 = __floats2half2_rn(e0, e1);
        __half2 h1 = __floats2half2_rn(e2, e3);
        __half2 h2 = __floats2half2_rn(e4, e5);
        __half2 h3 = __floats2half2_rn(e6, e7);
        uint4 o = make_uint4(*(u32*)&h0, *(u32*)&h1, *(u32*)&h2, *(u32*)&h3);
        ((uint4*)g_x16)[n * 16 + sub] = o;
    }
}

// ---------------- mean pool + fused head (last-block pattern) --------------
#define NPB 128
#define POOL_BLOCKS ((NN + NPB - 1) / NPB)
__global__ __launch_bounds__(64)
void k_poolhead(const float* __restrict__ lin_W, const float* __restrict__ lin_b,
                float* __restrict__ out) {
    __shared__ int sLast;
    int c2 = threadIdx.x;   // half2 column 0..63
    int n0 = blockIdx.x * NPB;
    int n1 = n0 + NPB; if (n1 > NN) n1 = NN;

    if (n0 < NN) {
        float ax = 0.f, ay = 0.f;
        int cur = g_batch[n0];
        int cnt = 0;
        for (int n = n0; n < n1; n++) {
            int g = g_batch[n];
            if (g != cur) {
                atomicAdd(&g_pool[cur * HH + 2 * c2], ax);
                atomicAdd(&g_pool[cur * HH + 2 * c2 + 1], ay);
                if (c2 == 0) atomicAdd(&g_cnt[cur], cnt);
                ax = 0.f; ay = 0.f; cnt = 0; cur = g;
            }
            u32 v = g_x16[n * 64 + c2];
            float2 f = __half22float2(*(const __half2*)&v);
            ax += f.x; ay += f.y;
            cnt++;
        }
        atomicAdd(&g_pool[cur * HH + 2 * c2], ax);
        atomicAdd(&g_pool[cur * HH + 2 * c2 + 1], ay);
        if (c2 == 0) atomicAdd(&g_cnt[cur], cnt);
    }

    __syncthreads();
    if (threadIdx.x == 0) {
        __threadfence();
        sLast = (atomicAdd(&g_pdone, 1) == POOL_BLOCKS - 1) ? 1 : 0;
    }
    __syncthreads();
    if (sLast) {
        __threadfence();
        int g = threadIdx.x;   // 0..63 graphs
        float inv = 1.f / fmaxf((float)g_cnt[g], 1.f);
        float a0 = 0.f, a1 = 0.f;
        #pragma unroll 8
        for (int c = 0; c < HH; c++) {
            float p = g_pool[g * HH + c] * inv;
            a0 += p * lin_W[c * 2 + 0];
            a1 += p * lin_W[c * 2 + 1];
        }
        out[g * 2 + 0] = a0 + lin_b[0];
        out[g * 2 + 1] = a1 + lin_b[1];
        if (threadIdx.x == 0) g_pdone = 0;   // reset for next replay
    }
}

// ---------------- launch ----------------
extern "C" void kernel_launch(void* const* d_in, const int* in_sizes, int n_in,
                              void* d_out, int out_size) {
    const float* x     = (const float*)d_in[0];
    const void*  ei    = d_in[1];
    const void*  batch = d_in[2];
    const float* W1 = (const float*)d_in[3];
    const float* b1 = (const float*)d_in[4];
    const float* W2 = (const float*)d_in[5];
    const float* b2 = (const float*)d_in[6];
    const float* W3 = (const float*)d_in[7];
    const float* b3 = (const float*)d_in[8];
    const float* lin_W = (const float*)d_in[9];
    const float* lin_b = (const float*)d_in[10];
    const float* bn1g = (const float*)d_in[11];
    const float* bn1b = (const float*)d_in[12];
    const float* bn1m = (const float*)d_in[13];
    const float* bn1v = (const float*)d_in[14];
    const float* bn2g = (const float*)d_in[15];
    const float* bn2b = (const float*)d_in[16];
    const float* bn2m = (const float*)d_in[17];
    const float* bn2v = (const float*)d_in[18];
    const float* bn3g = (const float*)d_in[19];
    const float* bn3b = (const float*)d_in[20];
    const float* bn3m = (const float*)d_in[21];
    const float* bn3v = (const float*)d_in[22];
    float* out = (float*)d_out;

    const int TB = 256;
    const int ebl  = (NE + TB - 1) / TB;
    const int e2bl = (NE / 2 + TB - 1) / TB;
    const int nbl = (NN + TB - 1) / TB;
    const int abl = (NN * 32 + TB - 1) / TB;

    k_init<<<nbl, TB>>>(ei, batch, W2, W3,                     // 0
                        b1, bn1g, bn1b, bn1m, bn1v,
                        b2, bn2g, bn2b, bn2m, bn2v,
                        b3, bn3g, bn3b, bn3m, bn3v);
    k_cvt_count<<<e2bl, TB>>>(ei);                             // 1
    k_scan1<<<NSB, SCAN_B>>>();                                // 2
    k_scan3<<<nbl, TB>>>(x);                                   // 3
    k_fill<<<ebl, TB>>>(ei);                                   // 4

    k_l1<<<(NN + 63) / 64, 256>>>(W1);                         // 5  -> g_x16 (BN1)

    k_gemmh<<<(NN + 127) / 128, 256>>>(0);                     // 6  -> g_h16
    k_agg16<<<abl, TB>>>(1);                                   // 7  -> g_x16 (BN2)

    k_gemmh<<<(NN + 127) / 128, 256>>>(1);                     // 8  -> g_h16
    k_agg16<<<abl, TB>>>(2);                                   // 9  -> g_x16 (BN3)

    k_poolhead<<<POOL_BLOCKS, 64>>>(lin_W, lin_b, out);        // 10
}